// round 5
// baseline (speedup 1.0000x reference)
#include <cuda_runtime.h>
#include <cuda_bf16.h>
#include <cstdint>

// Problem constants
#define BDIM 2
#define VDIM 8
#define PDIM 4096
#define DDIM 1024
#define NREF 256
#define EN   16384
#define NCAND 8
#define NCT  128          // EN / 128 column tiles

// Scratch (device globals: allocation-free)
__device__ float g_pval[BDIM * NREF * NCT * 4 * 8];   // 8 MB
__device__ int   g_pidx[BDIM * NREF * NCT * 4 * 8];   // 8 MB
__device__ int   g_topk[BDIM * NREF * 4];
__device__ float g_accum[3];

__constant__ int c_ST[3] = {2, 4, 6};   // SHARED_TEACHER
__constant__ int c_SS[3] = {1, 2, 3};   // SHARED_STUDENT

__device__ __forceinline__ void ins8(float x, int e, float* v, int* id) {
    if (x <= v[7]) return;
    v[7] = x; id[7] = e;
    #pragma unroll
    for (int j = 7; j >= 1; j--) {
        if (v[j] > v[j - 1]) {
            float tv = v[j]; v[j] = v[j - 1]; v[j - 1] = tv;
            int ti = id[j]; id[j] = id[j - 1]; id[j - 1] = ti;
        }
    }
}

// ---------------------------------------------------------------------------
// K1: sim GEMM (mma.sync bf16, fp32 accum), fused f32->bf16 convert, fused
//     B-row norm, fused per-row top-8 candidate partials (no g_sim).
// 128x128 block tile, BK=32, 2-stage smem pipeline, 8 warps, warp tile 64x32.
// NO occupancy cap: registers must stay spill-free (R4 lesson).
// ---------------------------------------------------------------------------
#define GBK 32
#define SROW 40                              // halves per smem row (32 + 8 pad)
#define STAGE_BYTES 20480                    // A 10240 + B 10240
#define GEMM_SMEM (2 * STAGE_BYTES)          // 40960; epilogue reuses as 64x129 f32

__global__ void __launch_bounds__(256, 1)
k_gemm(const float* __restrict__ teacher, const int* __restrict__ ref_perm) {
    extern __shared__ __align__(16) char dsmem[];
    __shared__ float s_inv[128];

    const int b     = blockIdx.z;
    const int rbase = blockIdx.y * 128;
    const int ct    = blockIdx.x;
    const int ebase = ct * 128;
    const int tid   = threadIdx.x;
    const int lane  = tid & 31;
    const int wid   = tid >> 5;
    const int wm    = (wid >> 2) * 64;
    const int wn    = (wid & 3) * 32;
    const uint32_t sbase = (uint32_t)__cvta_generic_to_shared(dsmem);

    // global loaders: thread t -> row t>>1, k-segment (t&1)*16
    const int lrow = tid >> 1;
    const int lseg = (tid & 1) * 16;

    const float* aptr = teacher + ((size_t)(b * VDIM) * PDIM + ref_perm[rbase + lrow]) * DDIM + lseg;
    const int v = 2 * (ebase >> 12) + 1;           // EXTRA_FRAMES {1,3,5,7}
    const int p = (ebase & (PDIM - 1)) + lrow;
    const float* bptr = teacher + ((size_t)(b * VDIM + v) * PDIM + p) * DDIM + lseg;

    float acc[4][4][4];
    #pragma unroll
    for (int i = 0; i < 4; i++)
        #pragma unroll
        for (int j = 0; j < 4; j++)
            #pragma unroll
            for (int k = 0; k < 4; k++) acc[i][j][k] = 0.f;

    uint2 pfa[4], pfb[4];
    float ssq = 0.f;

    // ldmatrix lane addressing (offsets within a stage)
    const int g  = lane >> 3;
    const int xr = (lane & 7) + (g & 1) * 8;
    const int xk = (g >> 1) * 8;
    uint32_t a_off[4], b_off[2];
    #pragma unroll
    for (int mi = 0; mi < 4; mi++)
        a_off[mi] = (uint32_t)((wm + mi * 16 + xr) * SROW + xk) * 2;
    #pragma unroll
    for (int nj = 0; nj < 2; nj++)
        b_off[nj] = 10240u + (uint32_t)((wn + nj * 16 + xr) * SROW + xk) * 2;

    const uint32_t st_a = (uint32_t)(lrow * SROW + lseg) * 2;
    const uint32_t st_b = st_a + 10240u;

    // initial prefetch (kt = 0)
    #pragma unroll
    for (int i = 0; i < 4; i++) {
        float4 xa = *(const float4*)(aptr + i * 4);
        float4 xb = *(const float4*)(bptr + i * 4);
        ssq += xb.x * xb.x + xb.y * xb.y + xb.z * xb.z + xb.w * xb.w;
        __nv_bfloat162 a0, a1, b0, b1;
        a0.x = __float2bfloat16(xa.x); a0.y = __float2bfloat16(xa.y);
        a1.x = __float2bfloat16(xa.z); a1.y = __float2bfloat16(xa.w);
        b0.x = __float2bfloat16(xb.x); b0.y = __float2bfloat16(xb.y);
        b1.x = __float2bfloat16(xb.z); b1.y = __float2bfloat16(xb.w);
        pfa[i] = make_uint2(*(uint32_t*)&a0, *(uint32_t*)&a1);
        pfb[i] = make_uint2(*(uint32_t*)&b0, *(uint32_t*)&b1);
    }

    for (int kt = 0; kt < DDIM / GBK; kt++) {
        const uint32_t stg = (kt & 1) * STAGE_BYTES;
        char* stage = dsmem + stg;
        #pragma unroll
        for (int i = 0; i < 4; i++) {
            *(uint2*)(stage + st_a + i * 8) = pfa[i];
            *(uint2*)(stage + st_b + i * 8) = pfb[i];
        }
        __syncthreads();

        if (kt + 1 < DDIM / GBK) {
            const float* ap = aptr + (kt + 1) * GBK;
            const float* bp = bptr + (kt + 1) * GBK;
            #pragma unroll
            for (int i = 0; i < 4; i++) {
                float4 xa = *(const float4*)(ap + i * 4);
                float4 xb = *(const float4*)(bp + i * 4);
                ssq += xb.x * xb.x + xb.y * xb.y + xb.z * xb.z + xb.w * xb.w;
                __nv_bfloat162 a0, a1, b0, b1;
                a0.x = __float2bfloat16(xa.x); a0.y = __float2bfloat16(xa.y);
                a1.x = __float2bfloat16(xa.z); a1.y = __float2bfloat16(xa.w);
                b0.x = __float2bfloat16(xb.x); b0.y = __float2bfloat16(xb.y);
                b1.x = __float2bfloat16(xb.z); b1.y = __float2bfloat16(xb.w);
                pfa[i] = make_uint2(*(uint32_t*)&a0, *(uint32_t*)&a1);
                pfb[i] = make_uint2(*(uint32_t*)&b0, *(uint32_t*)&b1);
            }
        }

        #pragma unroll
        for (int ks = 0; ks < GBK; ks += 16) {
            uint32_t af[4][4], bf[2][4];
            #pragma unroll
            for (int mi = 0; mi < 4; mi++) {
                asm volatile("ldmatrix.sync.aligned.m8n8.x4.shared.b16 {%0,%1,%2,%3}, [%4];"
                    : "=r"(af[mi][0]), "=r"(af[mi][1]), "=r"(af[mi][2]), "=r"(af[mi][3])
                    : "r"(sbase + stg + a_off[mi] + ks * 2));
            }
            #pragma unroll
            for (int nj = 0; nj < 2; nj++) {
                asm volatile("ldmatrix.sync.aligned.m8n8.x4.shared.b16 {%0,%1,%2,%3}, [%4];"
                    : "=r"(bf[nj][0]), "=r"(bf[nj][1]), "=r"(bf[nj][2]), "=r"(bf[nj][3])
                    : "r"(sbase + stg + b_off[nj] + ks * 2));
            }
            #pragma unroll
            for (int mi = 0; mi < 4; mi++) {
                #pragma unroll
                for (int nj = 0; nj < 4; nj++) {
                    uint32_t bb0 = bf[nj >> 1][nj & 1];
                    uint32_t bb1 = bf[nj >> 1][(nj & 1) + 2];
                    asm volatile(
                        "mma.sync.aligned.m16n8k16.row.col.f32.bf16.bf16.f32 "
                        "{%0,%1,%2,%3}, {%4,%5,%6,%7}, {%8,%9}, {%0,%1,%2,%3};"
                        : "+f"(acc[mi][nj][0]), "+f"(acc[mi][nj][1]),
                          "+f"(acc[mi][nj][2]), "+f"(acc[mi][nj][3])
                        : "r"(af[mi][0]), "r"(af[mi][1]), "r"(af[mi][2]), "r"(af[mi][3]),
                          "r"(bb0), "r"(bb1));
                }
            }
        }
    }

    // B-row inverse norms (exact, from f32): pair (2r, 2r+1)
    ssq += __shfl_xor_sync(0xffffffffu, ssq, 1);
    if ((tid & 1) == 0) s_inv[lrow] = 1.0f / fmaxf(sqrtf(ssq), 1e-12f);

    // epilogue: 2 chunks of 64 rows staged in smem; fused top-8 per 32 cols
    float (*C)[129] = (float (*)[129])dsmem;
    const int erow = tid & 63;
    const int q    = tid >> 6;

    #pragma unroll
    for (int chunk = 0; chunk < 2; chunk++) {
        __syncthreads();
        if ((wm >> 6) == chunk) {
            #pragma unroll
            for (int mi = 0; mi < 4; mi++) {
                int lr = mi * 16 + (lane >> 2);
                #pragma unroll
                for (int nj = 0; nj < 4; nj++) {
                    int cc = wn + nj * 8 + (lane & 3) * 2;
                    C[lr][cc]         = acc[mi][nj][0] * s_inv[cc];
                    C[lr][cc + 1]     = acc[mi][nj][1] * s_inv[cc + 1];
                    C[lr + 8][cc]     = acc[mi][nj][2] * s_inv[cc];
                    C[lr + 8][cc + 1] = acc[mi][nj][3] * s_inv[cc + 1];
                }
            }
        }
        __syncthreads();

        float bv[8]; int bi[8];
        #pragma unroll
        for (int j = 0; j < 8; j++) { bv[j] = -3.4e38f; bi[j] = 0; }
        #pragma unroll
        for (int j = 0; j < 32; j++) {
            int c = q * 32 + j;
            ins8(C[erow][c], ebase + c, bv, bi);
        }
        int gr = rbase + chunk * 64 + erow;
        size_t o = ((((size_t)(b * NREF + gr)) * NCT + ct) * 4 + q) * 8;
        #pragma unroll
        for (int j = 0; j < 8; j++) { g_pval[o + j] = bv[j]; g_pidx[o + j] = bi[j]; }
    }
}

// ---------------------------------------------------------------------------
// K2: per (b,r): merge 512 partial top-8s -> 8 candidates -> exact fp32
//     re-rank -> exact top-4 indices. One block does everything.
// ---------------------------------------------------------------------------
__global__ void __launch_bounds__(256)
k_select(const float* __restrict__ teacher, const int* __restrict__ ref_perm) {
    int r = blockIdx.x, b = blockIdx.y, tid = threadIdx.x;
    int w = tid >> 5, lane = tid & 31;
    size_t base = ((size_t)(b * NREF + r)) * (NCT * 4 * 8);

    if (r == 0 && b == 0 && tid < 3) g_accum[tid] = 0.f;

    // phase 1: merge partials
    float v[8]; int id[8];
    #pragma unroll
    for (int j = 0; j < 8; j++) { v[j] = -3.4e38f; id[j] = 0; }
    for (int i = tid * 16; i < tid * 16 + 16; i++)
        ins8(g_pval[base + i], g_pidx[base + i], v, id);

    __shared__ float sv[2048];
    __shared__ int   si[2048];
    __shared__ float sv2[256];
    __shared__ int   si2[256];
    __shared__ int   s_cand[NCAND];
    __shared__ float s_sim[NCAND];
    __shared__ int   s_e[NCAND];

    #pragma unroll
    for (int j = 0; j < 8; j++) { sv[tid * 8 + j] = v[j]; si[tid * 8 + j] = id[j]; }
    __syncthreads();

    if (tid < 32) {
        float v2[8]; int id2[8];
        #pragma unroll
        for (int j = 0; j < 8; j++) { v2[j] = -3.4e38f; id2[j] = 0; }
        for (int t = tid * 64; t < tid * 64 + 64; t++) ins8(sv[t], si[t], v2, id2);
        #pragma unroll
        for (int j = 0; j < 8; j++) { sv2[tid * 8 + j] = v2[j]; si2[tid * 8 + j] = id2[j]; }
        __syncwarp();
        if (tid == 0) {
            float v3[8]; int id3[8];
            #pragma unroll
            for (int j = 0; j < 8; j++) { v3[j] = -3.4e38f; id3[j] = 0; }
            for (int t = 0; t < 256; t++) ins8(sv2[t], si2[t], v3, id3);
            #pragma unroll
            for (int j = 0; j < 8; j++) s_cand[j] = id3[j];
        }
    }
    __syncthreads();

    // phase 2: exact fp32 dot + norm for each candidate (warp w -> cand w)
    int e = s_cand[w];
    int vv = 2 * (e >> 12) + 1, p = e & (PDIM - 1);
    const float* er = teacher + ((size_t)(b * VDIM + vv) * PDIM + p) * DDIM;
    const float* rr = teacher + ((size_t)(b * VDIM) * PDIM + ref_perm[r]) * DDIM;

    float dot = 0.f, ss = 0.f;
    #pragma unroll
    for (int j = 0; j < 8; j++) {
        int idx = lane * 4 + j * 128;
        float4 x = *(const float4*)(er + idx);
        float4 y = *(const float4*)(rr + idx);
        dot += x.x * y.x + x.y * y.y + x.z * y.z + x.w * y.w;
        ss  += x.x * x.x + x.y * x.y + x.z * x.z + x.w * x.w;
    }
    #pragma unroll
    for (int o = 16; o; o >>= 1) {
        dot += __shfl_xor_sync(0xffffffffu, dot, o);
        ss  += __shfl_xor_sync(0xffffffffu, ss, o);
    }
    if (lane == 0) {
        s_sim[w] = dot / fmaxf(sqrtf(ss), 1e-12f);
        s_e[w] = e;
    }
    __syncthreads();

    // phase 3: exact top-4 of 8; ties -> smaller index (jax.lax.top_k order)
    if (tid == 0) {
        bool used[NCAND] = {false, false, false, false, false, false, false, false};
        #pragma unroll
        for (int j = 0; j < 4; j++) {
            int best = -1;
            float bvv = -3.4e38f; int be = 0x7fffffff;
            for (int t = 0; t < NCAND; t++) {
                if (used[t]) continue;
                if (s_sim[t] > bvv || (s_sim[t] == bvv && s_e[t] < be)) {
                    bvv = s_sim[t]; be = s_e[t]; best = t;
                }
            }
            used[best] = true;
            g_topk[(b * NREF + r) * 4 + j] = s_e[best];
        }
    }
}

// ---------------------------------------------------------------------------
// K3: KL + smooth-L1 losses. 64 threads (2 warps) per KL row-pair.
// ---------------------------------------------------------------------------
__global__ void __launch_bounds__(256)
k_loss(const float* __restrict__ teacher, const float* __restrict__ student,
       const int* __restrict__ ref_perm, const int* __restrict__ shared_perm) {
    __shared__ float sacc[3];
    __shared__ float r0[4][2], r1[4][2];
    int tid = threadIdx.x;
    if (tid < 3) sacc[tid] = 0.f;

    int grp  = tid >> 6;
    int sub  = tid & 63;
    int w2   = (tid >> 5) & 1;
    int lane = tid & 31;
    int w    = blockIdx.x * 4 + grp;

    const float *pa, *pb, *pc, *pd;
    int target;
    if (w < 1536) {
        target = 0;
        int i = w / 512, rem = w & 511;
        int b = rem >> 8, r = rem & 255;
        int rp = ref_perm[r], sp = shared_perm[r];
        pa = teacher + ((size_t)(b * VDIM) * PDIM + rp) * DDIM;
        pb = teacher + ((size_t)(b * VDIM + c_ST[i]) * PDIM + sp) * DDIM;
        pc = student + ((size_t)(b * 4) * PDIM + rp) * DDIM;
        pd = student + ((size_t)(b * 4 + c_SS[i]) * PDIM + sp) * DDIM;
    } else if (w < 3584) {
        target = 1;
        int t = w - 1536;
        int b = t >> 10, rem = t & 1023;
        int r = rem >> 2, k = rem & 3;
        int rp = ref_perm[r];
        int e = g_topk[((b << 8) + r) * 4 + k];
        int v = 2 * (e >> 12) + 1, p = e & (PDIM - 1);
        pa = teacher + ((size_t)(b * VDIM) * PDIM + rp) * DDIM;
        pc = student + ((size_t)(b * 4) * PDIM + rp) * DDIM;
        pb = pd = teacher + ((size_t)(b * VDIM + v) * PDIM + p) * DDIM;
    } else {
        target = 2;
        int t = w - 3584;
        int i = t >> 11, rem = t & 2047;
        int b = rem >> 10, r = (rem >> 2) & 255, k = rem & 3;
        int sp = shared_perm[r];
        int e = g_topk[((b << 8) + r) * 4 + k];
        int v = 2 * (e >> 12) + 1, p = e & (PDIM - 1);
        pa = teacher + ((size_t)(b * VDIM + c_ST[i]) * PDIM + sp) * DDIM;
        pc = student + ((size_t)(b * 4 + c_SS[i]) * PDIM + sp) * DDIM;
        pb = pd = teacher + ((size_t)(b * VDIM + v) * PDIM + p) * DDIM;
    }

    float dt[16], ds[16];
    bool same = (pb == pd);
    #pragma unroll
    for (int j = 0; j < 4; j++) {
        int idx = sub * 4 + j * 256;
        float4 A  = *(const float4*)(pa + idx);
        float4 Bv = *(const float4*)(pb + idx);
        float4 C  = *(const float4*)(pc + idx);
        float4 Dv = same ? Bv : *(const float4*)(pd + idx);
        dt[4 * j + 0] = A.x - Bv.x; dt[4 * j + 1] = A.y - Bv.y;
        dt[4 * j + 2] = A.z - Bv.z; dt[4 * j + 3] = A.w - Bv.w;
        ds[4 * j + 0] = C.x - Dv.x; ds[4 * j + 1] = C.y - Dv.y;
        ds[4 * j + 2] = C.z - Dv.z; ds[4 * j + 3] = C.w - Dv.w;
    }

    float mt = -3.4e38f, ms = -3.4e38f;
    #pragma unroll
    for (int i = 0; i < 16; i++) { mt = fmaxf(mt, dt[i]); ms = fmaxf(ms, ds[i]); }
    #pragma unroll
    for (int o = 16; o; o >>= 1) {
        mt = fmaxf(mt, __shfl_xor_sync(0xffffffffu, mt, o));
        ms = fmaxf(ms, __shfl_xor_sync(0xffffffffu, ms, o));
    }
    if (lane == 0) { r0[grp][w2] = mt; r1[grp][w2] = ms; }
    __syncthreads();
    mt = fmaxf(r0[grp][0], r0[grp][1]);
    ms = fmaxf(r1[grp][0], r1[grp][1]);

    float st = 0.f, ssum = 0.f;
    #pragma unroll
    for (int i = 0; i < 16; i++) { st += expf(dt[i] - mt); ssum += expf(ds[i] - ms); }
    #pragma unroll
    for (int o = 16; o; o >>= 1) {
        st   += __shfl_xor_sync(0xffffffffu, st, o);
        ssum += __shfl_xor_sync(0xffffffffu, ssum, o);
    }
    __syncthreads();
    if (lane == 0) { r0[grp][w2] = st; r1[grp][w2] = ssum; }
    __syncthreads();
    float lset = mt + logf(r0[grp][0] + r0[grp][1]);
    float lses = ms + logf(r1[grp][0] + r1[grp][1]);

    float acc = 0.f;
    #pragma unroll
    for (int i = 0; i < 16; i++) acc += expf(dt[i] - lset) * (dt[i] - ds[i]);
    #pragma unroll
    for (int o = 16; o; o >>= 1) acc += __shfl_xor_sync(0xffffffffu, acc, o);
    __syncthreads();
    if (lane == 0) r0[grp][w2] = acc;
    __syncthreads();

    if (sub == 0) {
        float kl = (r0[grp][0] + r0[grp][1]) - lset + lses;
        float ax = fabsf(kl);
        float sl = (ax < 0.5f) ? kl * kl : (ax - 0.25f);   // smooth_l1, beta=0.5
        atomicAdd(&sacc[target], sl);
    }
    __syncthreads();
    if (tid < 3) atomicAdd(&g_accum[tid], sacc[tid]);
}

// ---------------------------------------------------------------------------
// K4: final combine:  sum_d1/1536 + sum_d2/2048 + sum_d3/6144
// ---------------------------------------------------------------------------
__global__ void k_final(float* __restrict__ out) {
    out[0] = g_accum[0] * (1.0f / 1536.0f)
           + g_accum[1] * (1.0f / 2048.0f)
           + g_accum[2] * (1.0f / 6144.0f);
}

// ---------------------------------------------------------------------------
extern "C" void kernel_launch(void* const* d_in, const int* in_sizes, int n_in,
                              void* d_out, int out_size) {
    const float* teacher     = (const float*)d_in[0];
    const float* student     = (const float*)d_in[1];
    const int*   ref_perm    = (const int*)d_in[2];
    const int*   shared_perm = (const int*)d_in[3];
    float* out = (float*)d_out;

    k_gemm<<<dim3(NCT, NREF / 128, BDIM), 256, GEMM_SMEM>>>(teacher, ref_perm);
    k_select<<<dim3(NREF, BDIM), 256>>>(teacher, ref_perm);
    k_loss<<<9728 / 4, 256>>>(teacher, student, ref_perm, shared_perm);
    k_final<<<1, 1>>>(out);
}

// round 6
// speedup vs baseline: 1.0618x; 1.0618x over previous
#include <cuda_runtime.h>
#include <cuda_bf16.h>
#include <cstdint>

// Problem constants
#define BDIM 2
#define VDIM 8
#define PDIM 4096
#define DDIM 1024
#define NREF 256
#define EN   16384
#define NCAND 8
#define NCT  128          // EN / 128 column tiles

// Scratch (device globals: allocation-free)
__device__ __nv_bfloat16 g_bbf[BDIM * EN * DDIM];     // 67 MB converted extra frames
__device__ __nv_bfloat16 g_abf[BDIM * NREF * DDIM];   // 1 MB gathered+converted refs
__device__ float g_inv[BDIM * EN];
__device__ float g_pval[BDIM * NREF * NCT * 4 * 8];   // 8 MB
__device__ int   g_pidx[BDIM * NREF * NCT * 4 * 8];   // 8 MB
__device__ int   g_topk[BDIM * NREF * 4];
__device__ float g_accum[3];

__constant__ int c_ST[3] = {2, 4, 6};   // SHARED_TEACHER
__constant__ int c_SS[3] = {1, 2, 3};   // SHARED_STUDENT

__device__ __forceinline__ void ins8(float x, int e, float* v, int* id) {
    if (x <= v[7]) return;
    v[7] = x; id[7] = e;
    #pragma unroll
    for (int j = 7; j >= 1; j--) {
        if (v[j] > v[j - 1]) {
            float tv = v[j]; v[j] = v[j - 1]; v[j - 1] = tv;
            int ti = id[j]; id[j] = id[j - 1]; id[j - 1] = ti;
        }
    }
}

// ---------------------------------------------------------------------------
// K0: convert teacher rows to bf16 once (+ exact f32 inverse norms for B rows)
//   blocks [0, B*EN):            extra-frame rows -> g_bbf + g_inv
//   blocks [B*EN, B*EN+B*NREF):  gathered ref rows -> g_abf
// ---------------------------------------------------------------------------
__global__ void __launch_bounds__(128)
k_convert(const float* __restrict__ teacher, const int* __restrict__ ref_perm) {
    const int id  = blockIdx.x;
    const int tid = threadIdx.x;

    const float* src;
    __nv_bfloat16* dst;
    bool donorm;
    int nidx = 0;
    if (id < BDIM * EN) {
        int b = id >> 14, e = id & (EN - 1);
        int v = 2 * (e >> 12) + 1, p = e & (PDIM - 1);
        src = teacher + ((size_t)(b * VDIM + v) * PDIM + p) * DDIM;
        dst = g_bbf + (size_t)id * DDIM;
        donorm = true; nidx = id;
    } else {
        int t = id - BDIM * EN;
        int b = t >> 8, r = t & 255;
        src = teacher + ((size_t)(b * VDIM) * PDIM + ref_perm[r]) * DDIM;
        dst = g_abf + (size_t)t * DDIM;
        donorm = false;
    }

    float4 x0 = ((const float4*)src)[tid * 2];
    float4 x1 = ((const float4*)src)[tid * 2 + 1];
    __nv_bfloat162 h0, h1, h2, h3;
    h0.x = __float2bfloat16(x0.x); h0.y = __float2bfloat16(x0.y);
    h1.x = __float2bfloat16(x0.z); h1.y = __float2bfloat16(x0.w);
    h2.x = __float2bfloat16(x1.x); h2.y = __float2bfloat16(x1.y);
    h3.x = __float2bfloat16(x1.z); h3.y = __float2bfloat16(x1.w);
    uint4 pk;
    pk.x = *(uint32_t*)&h0; pk.y = *(uint32_t*)&h1;
    pk.z = *(uint32_t*)&h2; pk.w = *(uint32_t*)&h3;
    ((uint4*)dst)[tid] = pk;

    if (donorm) {
        float ss = x0.x * x0.x + x0.y * x0.y + x0.z * x0.z + x0.w * x0.w
                 + x1.x * x1.x + x1.y * x1.y + x1.z * x1.z + x1.w * x1.w;
        #pragma unroll
        for (int o = 16; o; o >>= 1) ss += __shfl_xor_sync(0xffffffffu, ss, o);
        __shared__ float sh[4];
        if ((tid & 31) == 0) sh[tid >> 5] = ss;
        __syncthreads();
        if (tid == 0) {
            float t = sh[0] + sh[1] + sh[2] + sh[3];
            g_inv[nidx] = 1.0f / fmaxf(sqrtf(t), 1e-12f);
        }
    }
}

// ---------------------------------------------------------------------------
// K1: sim GEMM (mma.sync bf16->fp32), bf16 inputs, register-only fused
//     top-8 epilogue. 128x128 tile, BK=32, single smem buffer + reg prefetch
//     (proven R2 mainloop), occupancy 2.
// ---------------------------------------------------------------------------
#define GBK 32
#define SROW 40   // halves per smem row (32 data + 8 pad); 80B rows

__global__ void __launch_bounds__(256, 2)
k_gemm() {
    __shared__ __align__(16) __nv_bfloat16 As[128][SROW];
    __shared__ __align__(16) __nv_bfloat16 Bs[128][SROW];
    __shared__ float s_inv[128];

    const int b     = blockIdx.z;
    const int rbase = blockIdx.y * 128;
    const int ct    = blockIdx.x;
    const int ebase = ct * 128;
    const int tid   = threadIdx.x;
    const int lane  = tid & 31;
    const int wid   = tid >> 5;
    const int wm    = (wid >> 2) * 64;
    const int wn    = (wid & 3) * 32;

    // loaders: thread t -> row t>>1, halves [(t&1)*16, +16)
    const int lrow = tid >> 1;
    const int lseg = (tid & 1) * 16;

    const __nv_bfloat16* aptr = g_abf + ((size_t)(b * NREF + rbase + lrow)) * DDIM + lseg;
    const __nv_bfloat16* bptr = g_bbf + ((size_t)(b * EN + ebase + lrow)) * DDIM + lseg;

    float acc[4][4][4];
    #pragma unroll
    for (int i = 0; i < 4; i++)
        #pragma unroll
        for (int j = 0; j < 4; j++)
            #pragma unroll
            for (int k = 0; k < 4; k++) acc[i][j][k] = 0.f;

    uint4 pfa0, pfa1, pfb0, pfb1;

    // ldmatrix lane addressing
    const int g  = lane >> 3;
    const int xr = (lane & 7) + (g & 1) * 8;
    const int xk = (g >> 1) * 8;
    uint32_t a_base[4], b_base[2];
    #pragma unroll
    for (int mi = 0; mi < 4; mi++)
        a_base[mi] = (uint32_t)__cvta_generic_to_shared(&As[wm + mi * 16 + xr][xk]);
    #pragma unroll
    for (int nj = 0; nj < 2; nj++)
        b_base[nj] = (uint32_t)__cvta_generic_to_shared(&Bs[wn + nj * 16 + xr][xk]);

    // initial prefetch (kt = 0)
    pfa0 = ((const uint4*)aptr)[0]; pfa1 = ((const uint4*)aptr)[1];
    pfb0 = ((const uint4*)bptr)[0]; pfb1 = ((const uint4*)bptr)[1];

    for (int kt = 0; kt < DDIM / GBK; kt++) {
        *(uint4*)&As[lrow][lseg]     = pfa0;
        *(uint4*)&As[lrow][lseg + 8] = pfa1;
        *(uint4*)&Bs[lrow][lseg]     = pfb0;
        *(uint4*)&Bs[lrow][lseg + 8] = pfb1;
        __syncthreads();

        if (kt + 1 < DDIM / GBK) {
            const __nv_bfloat16* ap = aptr + (kt + 1) * GBK;
            const __nv_bfloat16* bp = bptr + (kt + 1) * GBK;
            pfa0 = ((const uint4*)ap)[0]; pfa1 = ((const uint4*)ap)[1];
            pfb0 = ((const uint4*)bp)[0]; pfb1 = ((const uint4*)bp)[1];
        }

        #pragma unroll
        for (int ks = 0; ks < GBK; ks += 16) {
            uint32_t af[4][4], bf[2][4];
            #pragma unroll
            for (int mi = 0; mi < 4; mi++) {
                asm volatile("ldmatrix.sync.aligned.m8n8.x4.shared.b16 {%0,%1,%2,%3}, [%4];"
                    : "=r"(af[mi][0]), "=r"(af[mi][1]), "=r"(af[mi][2]), "=r"(af[mi][3])
                    : "r"(a_base[mi] + ks * 2));
            }
            #pragma unroll
            for (int nj = 0; nj < 2; nj++) {
                asm volatile("ldmatrix.sync.aligned.m8n8.x4.shared.b16 {%0,%1,%2,%3}, [%4];"
                    : "=r"(bf[nj][0]), "=r"(bf[nj][1]), "=r"(bf[nj][2]), "=r"(bf[nj][3])
                    : "r"(b_base[nj] + ks * 2));
            }
            #pragma unroll
            for (int mi = 0; mi < 4; mi++) {
                #pragma unroll
                for (int nj = 0; nj < 4; nj++) {
                    uint32_t bb0 = bf[nj >> 1][nj & 1];
                    uint32_t bb1 = bf[nj >> 1][(nj & 1) + 2];
                    asm volatile(
                        "mma.sync.aligned.m16n8k16.row.col.f32.bf16.bf16.f32 "
                        "{%0,%1,%2,%3}, {%4,%5,%6,%7}, {%8,%9}, {%0,%1,%2,%3};"
                        : "+f"(acc[mi][nj][0]), "+f"(acc[mi][nj][1]),
                          "+f"(acc[mi][nj][2]), "+f"(acc[mi][nj][3])
                        : "r"(af[mi][0]), "r"(af[mi][1]), "r"(af[mi][2]), "r"(af[mi][3]),
                          "r"(bb0), "r"(bb1));
                }
            }
        }
        __syncthreads();
    }

    // inverse norms for this column tile
    if (tid < 128) s_inv[tid] = g_inv[b * EN + ebase + tid];
    __syncthreads();

    // register-only epilogue: per (row, 32-col warp span) top-8 via shfl merge
    const int q = wid & 3;                    // warp-n-group (cols wn..wn+31)
    #pragma unroll
    for (int mi = 0; mi < 4; mi++) {
        #pragma unroll
        for (int h = 0; h < 2; h++) {
            int row_local = wm + mi * 16 + (lane >> 2) + h * 8;
            float v8[8]; int i8[8];
            #pragma unroll
            for (int j = 0; j < 8; j++) { v8[j] = -3.4e38f; i8[j] = 0; }
            #pragma unroll
            for (int nj = 0; nj < 4; nj++) {
                int c0 = wn + nj * 8 + (lane & 3) * 2;
                ins8(acc[mi][nj][h * 2 + 0] * s_inv[c0],     ebase + c0,     v8, i8);
                ins8(acc[mi][nj][h * 2 + 1] * s_inv[c0 + 1], ebase + c0 + 1, v8, i8);
            }
            // merge across the 4 lanes holding this row (lane&3 = 0..3)
            #pragma unroll
            for (int off = 1; off <= 2; off <<= 1) {
                float tv[8]; int ti[8];
                #pragma unroll
                for (int j = 0; j < 8; j++) {
                    tv[j] = __shfl_xor_sync(0xffffffffu, v8[j], off);
                    ti[j] = __shfl_xor_sync(0xffffffffu, i8[j], off);
                }
                #pragma unroll
                for (int j = 0; j < 8; j++) ins8(tv[j], ti[j], v8, i8);
            }
            if ((lane & 3) == 0) {
                int gr = rbase + row_local;
                size_t o = ((((size_t)(b * NREF + gr)) * NCT + ct) * 4 + q) * 8;
                #pragma unroll
                for (int j = 0; j < 8; j++) { g_pval[o + j] = v8[j]; g_pidx[o + j] = i8[j]; }
            }
        }
    }
}

// ---------------------------------------------------------------------------
// K2: per (b,r): merge 512 partial top-8s -> 8 candidates -> exact fp32
//     re-rank -> exact top-4 indices.
// ---------------------------------------------------------------------------
__global__ void __launch_bounds__(256)
k_select(const float* __restrict__ teacher, const int* __restrict__ ref_perm) {
    int r = blockIdx.x, b = blockIdx.y, tid = threadIdx.x;
    int w = tid >> 5, lane = tid & 31;
    size_t base = ((size_t)(b * NREF + r)) * (NCT * 4 * 8);

    if (r == 0 && b == 0 && tid < 3) g_accum[tid] = 0.f;

    float v[8]; int id[8];
    #pragma unroll
    for (int j = 0; j < 8; j++) { v[j] = -3.4e38f; id[j] = 0; }
    for (int i = tid * 16; i < tid * 16 + 16; i++)
        ins8(g_pval[base + i], g_pidx[base + i], v, id);

    __shared__ float sv[2048];
    __shared__ int   si[2048];
    __shared__ float sv2[256];
    __shared__ int   si2[256];
    __shared__ int   s_cand[NCAND];
    __shared__ float s_sim[NCAND];
    __shared__ int   s_e[NCAND];

    #pragma unroll
    for (int j = 0; j < 8; j++) { sv[tid * 8 + j] = v[j]; si[tid * 8 + j] = id[j]; }
    __syncthreads();

    if (tid < 32) {
        float v2[8]; int id2[8];
        #pragma unroll
        for (int j = 0; j < 8; j++) { v2[j] = -3.4e38f; id2[j] = 0; }
        for (int t = tid * 64; t < tid * 64 + 64; t++) ins8(sv[t], si[t], v2, id2);
        #pragma unroll
        for (int j = 0; j < 8; j++) { sv2[tid * 8 + j] = v2[j]; si2[tid * 8 + j] = id2[j]; }
        __syncwarp();
        if (tid == 0) {
            float v3[8]; int id3[8];
            #pragma unroll
            for (int j = 0; j < 8; j++) { v3[j] = -3.4e38f; id3[j] = 0; }
            for (int t = 0; t < 256; t++) ins8(sv2[t], si2[t], v3, id3);
            #pragma unroll
            for (int j = 0; j < 8; j++) s_cand[j] = id3[j];
        }
    }
    __syncthreads();

    // exact fp32 dot + norm for each candidate (warp w -> cand w)
    int e = s_cand[w];
    int vv = 2 * (e >> 12) + 1, p = e & (PDIM - 1);
    const float* er = teacher + ((size_t)(b * VDIM + vv) * PDIM + p) * DDIM;
    const float* rr = teacher + ((size_t)(b * VDIM) * PDIM + ref_perm[r]) * DDIM;

    float dot = 0.f, ss = 0.f;
    #pragma unroll
    for (int j = 0; j < 8; j++) {
        int idx = lane * 4 + j * 128;
        float4 x = *(const float4*)(er + idx);
        float4 y = *(const float4*)(rr + idx);
        dot += x.x * y.x + x.y * y.y + x.z * y.z + x.w * y.w;
        ss  += x.x * x.x + x.y * x.y + x.z * x.z + x.w * x.w;
    }
    #pragma unroll
    for (int o = 16; o; o >>= 1) {
        dot += __shfl_xor_sync(0xffffffffu, dot, o);
        ss  += __shfl_xor_sync(0xffffffffu, ss, o);
    }
    if (lane == 0) {
        s_sim[w] = dot / fmaxf(sqrtf(ss), 1e-12f);
        s_e[w] = e;
    }
    __syncthreads();

    if (tid == 0) {
        bool used[NCAND] = {false, false, false, false, false, false, false, false};
        #pragma unroll
        for (int j = 0; j < 4; j++) {
            int best = -1;
            float bvv = -3.4e38f; int be = 0x7fffffff;
            for (int t = 0; t < NCAND; t++) {
                if (used[t]) continue;
                if (s_sim[t] > bvv || (s_sim[t] == bvv && s_e[t] < be)) {
                    bvv = s_sim[t]; be = s_e[t]; best = t;
                }
            }
            used[best] = true;
            g_topk[(b * NREF + r) * 4 + j] = s_e[best];
        }
    }
}

// ---------------------------------------------------------------------------
// K3: KL + smooth-L1 losses. 64 threads (2 warps) per KL row-pair.
// ---------------------------------------------------------------------------
__global__ void __launch_bounds__(256)
k_loss(const float* __restrict__ teacher, const float* __restrict__ student,
       const int* __restrict__ ref_perm, const int* __restrict__ shared_perm) {
    __shared__ float sacc[3];
    __shared__ float r0[4][2], r1[4][2];
    int tid = threadIdx.x;
    if (tid < 3) sacc[tid] = 0.f;

    int grp  = tid >> 6;
    int sub  = tid & 63;
    int w2   = (tid >> 5) & 1;
    int lane = tid & 31;
    int w    = blockIdx.x * 4 + grp;

    const float *pa, *pb, *pc, *pd;
    int target;
    if (w < 1536) {
        target = 0;
        int i = w / 512, rem = w & 511;
        int b = rem >> 8, r = rem & 255;
        int rp = ref_perm[r], sp = shared_perm[r];
        pa = teacher + ((size_t)(b * VDIM) * PDIM + rp) * DDIM;
        pb = teacher + ((size_t)(b * VDIM + c_ST[i]) * PDIM + sp) * DDIM;
        pc = student + ((size_t)(b * 4) * PDIM + rp) * DDIM;
        pd = student + ((size_t)(b * 4 + c_SS[i]) * PDIM + sp) * DDIM;
    } else if (w < 3584) {
        target = 1;
        int t = w - 1536;
        int b = t >> 10, rem = t & 1023;
        int r = rem >> 2, k = rem & 3;
        int rp = ref_perm[r];
        int e = g_topk[((b << 8) + r) * 4 + k];
        int v = 2 * (e >> 12) + 1, p = e & (PDIM - 1);
        pa = teacher + ((size_t)(b * VDIM) * PDIM + rp) * DDIM;
        pc = student + ((size_t)(b * 4) * PDIM + rp) * DDIM;
        pb = pd = teacher + ((size_t)(b * VDIM + v) * PDIM + p) * DDIM;
    } else {
        target = 2;
        int t = w - 3584;
        int i = t >> 11, rem = t & 2047;
        int b = rem >> 10, r = (rem >> 2) & 255, k = rem & 3;
        int sp = shared_perm[r];
        int e = g_topk[((b << 8) + r) * 4 + k];
        int v = 2 * (e >> 12) + 1, p = e & (PDIM - 1);
        pa = teacher + ((size_t)(b * VDIM + c_ST[i]) * PDIM + sp) * DDIM;
        pc = student + ((size_t)(b * 4 + c_SS[i]) * PDIM + sp) * DDIM;
        pb = pd = teacher + ((size_t)(b * VDIM + v) * PDIM + p) * DDIM;
    }

    float dt[16], ds[16];
    bool same = (pb == pd);
    #pragma unroll
    for (int j = 0; j < 4; j++) {
        int idx = sub * 4 + j * 256;
        float4 A  = *(const float4*)(pa + idx);
        float4 Bv = *(const float4*)(pb + idx);
        float4 C  = *(const float4*)(pc + idx);
        float4 Dv = same ? Bv : *(const float4*)(pd + idx);
        dt[4 * j + 0] = A.x - Bv.x; dt[4 * j + 1] = A.y - Bv.y;
        dt[4 * j + 2] = A.z - Bv.z; dt[4 * j + 3] = A.w - Bv.w;
        ds[4 * j + 0] = C.x - Dv.x; ds[4 * j + 1] = C.y - Dv.y;
        ds[4 * j + 2] = C.z - Dv.z; ds[4 * j + 3] = C.w - Dv.w;
    }

    float mt = -3.4e38f, ms = -3.4e38f;
    #pragma unroll
    for (int i = 0; i < 16; i++) { mt = fmaxf(mt, dt[i]); ms = fmaxf(ms, ds[i]); }
    #pragma unroll
    for (int o = 16; o; o >>= 1) {
        mt = fmaxf(mt, __shfl_xor_sync(0xffffffffu, mt, o));
        ms = fmaxf(ms, __shfl_xor_sync(0xffffffffu, ms, o));
    }
    if (lane == 0) { r0[grp][w2] = mt; r1[grp][w2] = ms; }
    __syncthreads();
    mt = fmaxf(r0[grp][0], r0[grp][1]);
    ms = fmaxf(r1[grp][0], r1[grp][1]);

    float st = 0.f, ssum = 0.f;
    #pragma unroll
    for (int i = 0; i < 16; i++) { st += expf(dt[i] - mt); ssum += expf(ds[i] - ms); }
    #pragma unroll
    for (int o = 16; o; o >>= 1) {
        st   += __shfl_xor_sync(0xffffffffu, st, o);
        ssum += __shfl_xor_sync(0xffffffffu, ssum, o);
    }
    __syncthreads();
    if (lane == 0) { r0[grp][w2] = st; r1[grp][w2] = ssum; }
    __syncthreads();
    float lset = mt + logf(r0[grp][0] + r0[grp][1]);
    float lses = ms + logf(r1[grp][0] + r1[grp][1]);

    float acc = 0.f;
    #pragma unroll
    for (int i = 0; i < 16; i++) acc += expf(dt[i] - lset) * (dt[i] - ds[i]);
    #pragma unroll
    for (int o = 16; o; o >>= 1) acc += __shfl_xor_sync(0xffffffffu, acc, o);
    __syncthreads();
    if (lane == 0) r0[grp][w2] = acc;
    __syncthreads();

    if (sub == 0) {
        float kl = (r0[grp][0] + r0[grp][1]) - lset + lses;
        float ax = fabsf(kl);
        float sl = (ax < 0.5f) ? kl * kl : (ax - 0.25f);   // smooth_l1, beta=0.5
        atomicAdd(&sacc[target], sl);
    }
    __syncthreads();
    if (tid < 3) atomicAdd(&g_accum[tid], sacc[tid]);
}

// ---------------------------------------------------------------------------
// K4: final combine:  sum_d1/1536 + sum_d2/2048 + sum_d3/6144
// ---------------------------------------------------------------------------
__global__ void k_final(float* __restrict__ out) {
    out[0] = g_accum[0] * (1.0f / 1536.0f)
           + g_accum[1] * (1.0f / 2048.0f)
           + g_accum[2] * (1.0f / 6144.0f);
}

// ---------------------------------------------------------------------------
extern "C" void kernel_launch(void* const* d_in, const int* in_sizes, int n_in,
                              void* d_out, int out_size) {
    const float* teacher     = (const float*)d_in[0];
    const float* student     = (const float*)d_in[1];
    const int*   ref_perm    = (const int*)d_in[2];
    const int*   shared_perm = (const int*)d_in[3];
    float* out = (float*)d_out;

    k_convert<<<BDIM * EN + BDIM * NREF, 128>>>(teacher, ref_perm);
    k_gemm<<<dim3(NCT, NREF / 128, BDIM), 256>>>();
    k_select<<<dim3(NREF, BDIM), 256>>>(teacher, ref_perm);
    k_loss<<<9728 / 4, 256>>>(teacher, student, ref_perm, shared_perm);
    k_final<<<1, 1>>>(out);
}

// round 7
// speedup vs baseline: 1.5397x; 1.4501x over previous
#include <cuda_runtime.h>
#include <cuda_bf16.h>
#include <cstdint>

// Problem constants
#define BDIM 2
#define VDIM 8
#define PDIM 4096
#define DDIM 1024
#define NREF 256
#define EN   16384
#define NCAND 8

// Scratch (device globals: allocation-free)
__device__ float g_sim[BDIM * NREF * EN];        // 33.5 MB
__device__ int   g_topk[BDIM * NREF * 4];
__device__ float g_accum[3];

__constant__ int c_ST[3] = {2, 4, 6};   // SHARED_TEACHER
__constant__ int c_SS[3] = {1, 2, 3};   // SHARED_STUDENT

__device__ __forceinline__ void ins4(float x, int e, float* v, int* id) {
    if (x <= v[3]) return;
    v[3] = x; id[3] = e;
    #pragma unroll
    for (int j = 3; j >= 1; j--) {
        if (v[j] > v[j - 1]) {
            float tv = v[j]; v[j] = v[j - 1]; v[j - 1] = tv;
            int ti = id[j]; id[j] = id[j - 1]; id[j - 1] = ti;
        }
    }
}

__device__ __forceinline__ void ins8(float x, int e, float* v, int* id) {
    if (x <= v[7]) return;
    v[7] = x; id[7] = e;
    #pragma unroll
    for (int j = 7; j >= 1; j--) {
        if (v[j] > v[j - 1]) {
            float tv = v[j]; v[j] = v[j - 1]; v[j - 1] = tv;
            int ti = id[j]; id[j] = id[j - 1]; id[j - 1] = ti;
        }
    }
}

// ---------------------------------------------------------------------------
// K1: sim GEMM (mma.sync bf16, fp32 accum), fused f32->bf16 convert and
//     fused B-row norm. 128x128 CTA tile, BK=32, 512 threads, 16 warps,
//     warp tile 32x32 (low regs -> 16 warps/SM for latency hiding).
// ---------------------------------------------------------------------------
#define GBK 32
#define SROW 40   // halves per smem row (32 data + 8 pad); 80B, 16B-aligned

__device__ __forceinline__ uint4 cvt8(float4 x0, float4 x1) {
    __nv_bfloat162 h0, h1, h2, h3;
    h0.x = __float2bfloat16(x0.x); h0.y = __float2bfloat16(x0.y);
    h1.x = __float2bfloat16(x0.z); h1.y = __float2bfloat16(x0.w);
    h2.x = __float2bfloat16(x1.x); h2.y = __float2bfloat16(x1.y);
    h3.x = __float2bfloat16(x1.z); h3.y = __float2bfloat16(x1.w);
    uint4 r;
    r.x = *(uint32_t*)&h0; r.y = *(uint32_t*)&h1;
    r.z = *(uint32_t*)&h2; r.w = *(uint32_t*)&h3;
    return r;
}

__global__ void __launch_bounds__(512, 1)
k_gemm(const float* __restrict__ teacher, const int* __restrict__ ref_perm) {
    __shared__ __align__(16) __nv_bfloat16 As[128][SROW];
    __shared__ __align__(16) __nv_bfloat16 Bs[128][SROW];
    __shared__ float s_inv[128];

    const int b     = blockIdx.z;
    const int rbase = blockIdx.y * 128;
    const int ebase = blockIdx.x * 128;
    const int tid   = threadIdx.x;
    const int lane  = tid & 31;
    const int wid   = tid >> 5;          // 0..15
    const int wm    = (wid >> 2) * 32;   // 4 row groups of 32
    const int wn    = (wid & 3) * 32;    // 4 col groups of 32

    // loaders: thread t -> row t>>2, 8-float segment (t&3)*8
    const int lrow = tid >> 2;
    const int lseg = (tid & 3) * 8;

    const float* aptr = teacher + ((size_t)(b * VDIM) * PDIM + ref_perm[rbase + lrow]) * DDIM + lseg;
    const int v = 2 * (ebase >> 12) + 1;           // EXTRA_FRAMES {1,3,5,7}
    const int p = (ebase & (PDIM - 1)) + lrow;
    const float* bptr = teacher + ((size_t)(b * VDIM + v) * PDIM + p) * DDIM + lseg;

    float acc[2][4][4];
    #pragma unroll
    for (int i = 0; i < 2; i++)
        #pragma unroll
        for (int j = 0; j < 4; j++)
            #pragma unroll
            for (int k = 0; k < 4; k++) acc[i][j][k] = 0.f;

    uint4 pfa, pfb;
    float ssq = 0.f;

    // ldmatrix lane addressing
    const int g  = lane >> 3;
    const int xr = (lane & 7) + (g & 1) * 8;
    const int xk = (g >> 1) * 8;
    uint32_t a_base[2], b_base[2];
    #pragma unroll
    for (int mi = 0; mi < 2; mi++)
        a_base[mi] = (uint32_t)__cvta_generic_to_shared(&As[wm + mi * 16 + xr][xk]);
    #pragma unroll
    for (int nj = 0; nj < 2; nj++)
        b_base[nj] = (uint32_t)__cvta_generic_to_shared(&Bs[wn + nj * 16 + xr][xk]);

    // initial prefetch (kt = 0)
    {
        float4 xa0 = *(const float4*)(aptr);
        float4 xa1 = *(const float4*)(aptr + 4);
        float4 xb0 = *(const float4*)(bptr);
        float4 xb1 = *(const float4*)(bptr + 4);
        ssq += xb0.x * xb0.x + xb0.y * xb0.y + xb0.z * xb0.z + xb0.w * xb0.w
             + xb1.x * xb1.x + xb1.y * xb1.y + xb1.z * xb1.z + xb1.w * xb1.w;
        pfa = cvt8(xa0, xa1);
        pfb = cvt8(xb0, xb1);
    }

    for (int kt = 0; kt < DDIM / GBK; kt++) {
        *(uint4*)&As[lrow][lseg] = pfa;
        *(uint4*)&Bs[lrow][lseg] = pfb;
        __syncthreads();

        if (kt + 1 < DDIM / GBK) {
            const float* ap = aptr + (kt + 1) * GBK;
            const float* bp = bptr + (kt + 1) * GBK;
            float4 xa0 = *(const float4*)(ap);
            float4 xa1 = *(const float4*)(ap + 4);
            float4 xb0 = *(const float4*)(bp);
            float4 xb1 = *(const float4*)(bp + 4);
            ssq += xb0.x * xb0.x + xb0.y * xb0.y + xb0.z * xb0.z + xb0.w * xb0.w
                 + xb1.x * xb1.x + xb1.y * xb1.y + xb1.z * xb1.z + xb1.w * xb1.w;
            pfa = cvt8(xa0, xa1);
            pfb = cvt8(xb0, xb1);
        }

        #pragma unroll
        for (int ks = 0; ks < GBK; ks += 16) {
            uint32_t af[2][4], bf[2][4];
            #pragma unroll
            for (int mi = 0; mi < 2; mi++) {
                asm volatile("ldmatrix.sync.aligned.m8n8.x4.shared.b16 {%0,%1,%2,%3}, [%4];"
                    : "=r"(af[mi][0]), "=r"(af[mi][1]), "=r"(af[mi][2]), "=r"(af[mi][3])
                    : "r"(a_base[mi] + ks * 2));
            }
            #pragma unroll
            for (int nj = 0; nj < 2; nj++) {
                asm volatile("ldmatrix.sync.aligned.m8n8.x4.shared.b16 {%0,%1,%2,%3}, [%4];"
                    : "=r"(bf[nj][0]), "=r"(bf[nj][1]), "=r"(bf[nj][2]), "=r"(bf[nj][3])
                    : "r"(b_base[nj] + ks * 2));
            }
            #pragma unroll
            for (int mi = 0; mi < 2; mi++) {
                #pragma unroll
                for (int nj = 0; nj < 4; nj++) {
                    uint32_t bb0 = bf[nj >> 1][nj & 1];
                    uint32_t bb1 = bf[nj >> 1][(nj & 1) + 2];
                    asm volatile(
                        "mma.sync.aligned.m16n8k16.row.col.f32.bf16.bf16.f32 "
                        "{%0,%1,%2,%3}, {%4,%5,%6,%7}, {%8,%9}, {%0,%1,%2,%3};"
                        : "+f"(acc[mi][nj][0]), "+f"(acc[mi][nj][1]),
                          "+f"(acc[mi][nj][2]), "+f"(acc[mi][nj][3])
                        : "r"(af[mi][0]), "r"(af[mi][1]), "r"(af[mi][2]), "r"(af[mi][3]),
                          "r"(bb0), "r"(bb1));
                }
            }
        }
        __syncthreads();
    }

    // B-row inverse norms (exact, from f32): 4 threads per row
    ssq += __shfl_xor_sync(0xffffffffu, ssq, 1);
    ssq += __shfl_xor_sync(0xffffffffu, ssq, 2);
    if ((tid & 3) == 0) s_inv[lrow] = 1.0f / fmaxf(sqrtf(ssq), 1e-12f);
    __syncthreads();

    // epilogue: scale by inv_norm[e], write sim
    #pragma unroll
    for (int mi = 0; mi < 2; mi++) {
        int r = rbase + wm + mi * 16 + (lane >> 2);
        float* orow = g_sim + ((size_t)(b * NREF + r)) * EN + ebase;
        #pragma unroll
        for (int nj = 0; nj < 4; nj++) {
            int c = wn + nj * 8 + (lane & 3) * 2;
            float2 w0 = make_float2(acc[mi][nj][0] * s_inv[c], acc[mi][nj][1] * s_inv[c + 1]);
            float2 w1 = make_float2(acc[mi][nj][2] * s_inv[c], acc[mi][nj][3] * s_inv[c + 1]);
            *(float2*)(orow + c)          = w0;
            *(float2*)(orow + 8 * EN + c) = w1;
        }
    }
}

// ---------------------------------------------------------------------------
// K2: per (b,r): top-8 candidates from g_sim (R2-proven reduction) then
//     exact fp32 re-rank -> exact top-4 indices. One block per (r,b).
// ---------------------------------------------------------------------------
__global__ void __launch_bounds__(256)
k_select(const float* __restrict__ teacher, const int* __restrict__ ref_perm) {
    int r = blockIdx.x, b = blockIdx.y, tid = threadIdx.x;
    int w = tid >> 5, lane = tid & 31;
    const float* row = g_sim + ((size_t)(b * NREF + r)) * EN;

    if (r == 0 && b == 0 && tid < 3) g_accum[tid] = 0.f;

    // phase 1: per-thread top-4 over strided stripe (keeps any true top-4 elt)
    float v[4] = {-3.4e38f, -3.4e38f, -3.4e38f, -3.4e38f};
    int id[4] = {0, 0, 0, 0};
    for (int e = tid; e < EN; e += 256) ins4(row[e], e, v, id);

    __shared__ float sv[1024];
    __shared__ int   si[1024];
    __shared__ int   s_cand[NCAND];
    __shared__ float s_sim[NCAND];
    __shared__ int   s_e[NCAND];

    #pragma unroll
    for (int j = 0; j < 4; j++) { sv[tid * 4 + j] = v[j]; si[tid * 4 + j] = id[j]; }
    __syncthreads();

    if (tid < 32) {
        float v2[4] = {-3.4e38f, -3.4e38f, -3.4e38f, -3.4e38f};
        int id2[4] = {0, 0, 0, 0};
        for (int t = tid * 32; t < tid * 32 + 32; t++) ins4(sv[t], si[t], v2, id2);
        __syncwarp();
        #pragma unroll
        for (int j = 0; j < 4; j++) { sv[tid * 4 + j] = v2[j]; si[tid * 4 + j] = id2[j]; }
        __syncwarp();
        if (tid == 0) {
            float v3[8]; int id3[8];
            #pragma unroll
            for (int j = 0; j < 8; j++) { v3[j] = -3.4e38f; id3[j] = 0; }
            for (int t = 0; t < 128; t++) ins8(sv[t], si[t], v3, id3);
            #pragma unroll
            for (int j = 0; j < 8; j++) s_cand[j] = id3[j];
        }
    }
    __syncthreads();

    // phase 2: exact fp32 dot + norm per candidate (warp w -> cand w)
    int e = s_cand[w];
    int vv = 2 * (e >> 12) + 1, p = e & (PDIM - 1);
    const float* er = teacher + ((size_t)(b * VDIM + vv) * PDIM + p) * DDIM;
    const float* rr = teacher + ((size_t)(b * VDIM) * PDIM + ref_perm[r]) * DDIM;

    float dot = 0.f, ss = 0.f;
    #pragma unroll
    for (int j = 0; j < 8; j++) {
        int idx = lane * 4 + j * 128;
        float4 x = *(const float4*)(er + idx);
        float4 y = *(const float4*)(rr + idx);
        dot += x.x * y.x + x.y * y.y + x.z * y.z + x.w * y.w;
        ss  += x.x * x.x + x.y * x.y + x.z * x.z + x.w * x.w;
    }
    #pragma unroll
    for (int o = 16; o; o >>= 1) {
        dot += __shfl_xor_sync(0xffffffffu, dot, o);
        ss  += __shfl_xor_sync(0xffffffffu, ss, o);
    }
    if (lane == 0) {
        s_sim[w] = dot / fmaxf(sqrtf(ss), 1e-12f);
        s_e[w] = e;
    }
    __syncthreads();

    // phase 3: exact top-4 of 8; ties -> smaller index (jax.lax.top_k order)
    if (tid == 0) {
        bool used[NCAND] = {false, false, false, false, false, false, false, false};
        #pragma unroll
        for (int j = 0; j < 4; j++) {
            int best = -1;
            float bvv = -3.4e38f; int be = 0x7fffffff;
            for (int t = 0; t < NCAND; t++) {
                if (used[t]) continue;
                if (s_sim[t] > bvv || (s_sim[t] == bvv && s_e[t] < be)) {
                    bvv = s_sim[t]; be = s_e[t]; best = t;
                }
            }
            used[best] = true;
            g_topk[(b * NREF + r) * 4 + j] = s_e[best];
        }
    }
}

// ---------------------------------------------------------------------------
// K3: KL + smooth-L1 losses. 64 threads (2 warps) per KL row-pair (verified).
// ---------------------------------------------------------------------------
__global__ void __launch_bounds__(256)
k_loss(const float* __restrict__ teacher, const float* __restrict__ student,
       const int* __restrict__ ref_perm, const int* __restrict__ shared_perm) {
    __shared__ float sacc[3];
    __shared__ float r0[4][2], r1[4][2];
    int tid = threadIdx.x;
    if (tid < 3) sacc[tid] = 0.f;

    int grp  = tid >> 6;
    int sub  = tid & 63;
    int w2   = (tid >> 5) & 1;
    int lane = tid & 31;
    int w    = blockIdx.x * 4 + grp;

    const float *pa, *pb, *pc, *pd;
    int target;
    if (w < 1536) {
        target = 0;
        int i = w / 512, rem = w & 511;
        int b = rem >> 8, r = rem & 255;
        int rp = ref_perm[r], sp = shared_perm[r];
        pa = teacher + ((size_t)(b * VDIM) * PDIM + rp) * DDIM;
        pb = teacher + ((size_t)(b * VDIM + c_ST[i]) * PDIM + sp) * DDIM;
        pc = student + ((size_t)(b * 4) * PDIM + rp) * DDIM;
        pd = student + ((size_t)(b * 4 + c_SS[i]) * PDIM + sp) * DDIM;
    } else if (w < 3584) {
        target = 1;
        int t = w - 1536;
        int b = t >> 10, rem = t & 1023;
        int r = rem >> 2, k = rem & 3;
        int rp = ref_perm[r];
        int e = g_topk[((b << 8) + r) * 4 + k];
        int v = 2 * (e >> 12) + 1, p = e & (PDIM - 1);
        pa = teacher + ((size_t)(b * VDIM) * PDIM + rp) * DDIM;
        pc = student + ((size_t)(b * 4) * PDIM + rp) * DDIM;
        pb = pd = teacher + ((size_t)(b * VDIM + v) * PDIM + p) * DDIM;
    } else {
        target = 2;
        int t = w - 3584;
        int i = t >> 11, rem = t & 2047;
        int b = rem >> 10, r = (rem >> 2) & 255, k = rem & 3;
        int sp = shared_perm[r];
        int e = g_topk[((b << 8) + r) * 4 + k];
        int v = 2 * (e >> 12) + 1, p = e & (PDIM - 1);
        pa = teacher + ((size_t)(b * VDIM + c_ST[i]) * PDIM + sp) * DDIM;
        pc = student + ((size_t)(b * 4 + c_SS[i]) * PDIM + sp) * DDIM;
        pb = pd = teacher + ((size_t)(b * VDIM + v) * PDIM + p) * DDIM;
    }

    float dt[16], ds[16];
    bool same = (pb == pd);
    #pragma unroll
    for (int j = 0; j < 4; j++) {
        int idx = sub * 4 + j * 256;
        float4 A  = *(const float4*)(pa + idx);
        float4 Bv = *(const float4*)(pb + idx);
        float4 C  = *(const float4*)(pc + idx);
        float4 Dv = same ? Bv : *(const float4*)(pd + idx);
        dt[4 * j + 0] = A.x - Bv.x; dt[4 * j + 1] = A.y - Bv.y;
        dt[4 * j + 2] = A.z - Bv.z; dt[4 * j + 3] = A.w - Bv.w;
        ds[4 * j + 0] = C.x - Dv.x; ds[4 * j + 1] = C.y - Dv.y;
        ds[4 * j + 2] = C.z - Dv.z; ds[4 * j + 3] = C.w - Dv.w;
    }

    float mt = -3.4e38f, ms = -3.4e38f;
    #pragma unroll
    for (int i = 0; i < 16; i++) { mt = fmaxf(mt, dt[i]); ms = fmaxf(ms, ds[i]); }
    #pragma unroll
    for (int o = 16; o; o >>= 1) {
        mt = fmaxf(mt, __shfl_xor_sync(0xffffffffu, mt, o));
        ms = fmaxf(ms, __shfl_xor_sync(0xffffffffu, ms, o));
    }
    if (lane == 0) { r0[grp][w2] = mt; r1[grp][w2] = ms; }
    __syncthreads();
    mt = fmaxf(r0[grp][0], r0[grp][1]);
    ms = fmaxf(r1[grp][0], r1[grp][1]);

    float st = 0.f, ssum = 0.f;
    #pragma unroll
    for (int i = 0; i < 16; i++) { st += expf(dt[i] - mt); ssum += expf(ds[i] - ms); }
    #pragma unroll
    for (int o = 16; o; o >>= 1) {
        st   += __shfl_xor_sync(0xffffffffu, st, o);
        ssum += __shfl_xor_sync(0xffffffffu, ssum, o);
    }
    __syncthreads();
    if (lane == 0) { r0[grp][w2] = st; r1[grp][w2] = ssum; }
    __syncthreads();
    float lset = mt + logf(r0[grp][0] + r0[grp][1]);
    float lses = ms + logf(r1[grp][0] + r1[grp][1]);

    float acc = 0.f;
    #pragma unroll
    for (int i = 0; i < 16; i++) acc += expf(dt[i] - lset) * (dt[i] - ds[i]);
    #pragma unroll
    for (int o = 16; o; o >>= 1) acc += __shfl_xor_sync(0xffffffffu, acc, o);
    __syncthreads();
    if (lane == 0) r0[grp][w2] = acc;
    __syncthreads();

    if (sub == 0) {
        float kl = (r0[grp][0] + r0[grp][1]) - lset + lses;
        float ax = fabsf(kl);
        float sl = (ax < 0.5f) ? kl * kl : (ax - 0.25f);   // smooth_l1, beta=0.5
        atomicAdd(&sacc[target], sl);
    }
    __syncthreads();
    if (tid < 3) atomicAdd(&g_accum[tid], sacc[tid]);
}

// ---------------------------------------------------------------------------
// K4: final combine:  sum_d1/1536 + sum_d2/2048 + sum_d3/6144
// ---------------------------------------------------------------------------
__global__ void k_final(float* __restrict__ out) {
    out[0] = g_accum[0] * (1.0f / 1536.0f)
           + g_accum[1] * (1.0f / 2048.0f)
           + g_accum[2] * (1.0f / 6144.0f);
}

// ---------------------------------------------------------------------------
extern "C" void kernel_launch(void* const* d_in, const int* in_sizes, int n_in,
                              void* d_out, int out_size) {
    const float* teacher     = (const float*)d_in[0];
    const float* student     = (const float*)d_in[1];
    const int*   ref_perm    = (const int*)d_in[2];
    const int*   shared_perm = (const int*)d_in[3];
    float* out = (float*)d_out;

    k_gemm<<<dim3(EN / 128, NREF / 128, BDIM), 512>>>(teacher, ref_perm);
    k_select<<<dim3(NREF, BDIM), 256>>>(teacher, ref_perm);
    k_loss<<<9728 / 4, 256>>>(teacher, student, ref_perm, shared_perm);
    k_final<<<1, 1>>>(out);
}